// round 15
// baseline (speedup 1.0000x reference)
#include <cuda_runtime.h>
#include <cuda_bf16.h>
#include <math.h>

#define BATCH 131072

__device__ __nv_bfloat16 g_Cb[(size_t)BATCH * 320];
__device__ __nv_bfloat16 g_Hb[(size_t)BATCH * 256];
__device__ __nv_bfloat16 g_tokb[(size_t)BATCH * 512];
__device__ __nv_bfloat16 g_wtokb[(size_t)BATCH * 256];
__device__ float g_raw[BATCH];
__device__ float g_part[256];
__device__ float g_scalars[2];
__device__ float g_A1T[12 * 256];
__device__ float g_c1[256];
__device__ __nv_bfloat16 g_Gb[64 * 256];
__device__ float g_cb[64];
__device__ __nv_bfloat16 g_W2b[512 * 256];
__device__ __nv_bfloat16 g_W1b[256 * 320];

// ---------------- helpers ----------------
__device__ __forceinline__ void cp16(unsigned dst, const void* src) {
    asm volatile("cp.async.cg.shared.global [%0], [%1], 16;" ::
                 "r"(dst), "l"(src));
}
#define CP_COMMIT asm volatile("cp.async.commit_group;")
#define CP_WAIT0  asm volatile("cp.async.wait_group 0;")
#define CP_WAIT1  asm volatile("cp.async.wait_group 1;")

__device__ __forceinline__ void mma16(float* d, const unsigned* a, const unsigned* b) {
    asm volatile(
        "mma.sync.aligned.m16n8k16.row.col.f32.bf16.bf16.f32 "
        "{%0,%1,%2,%3}, {%4,%5,%6,%7}, {%8,%9}, {%0,%1,%2,%3};"
        : "+f"(d[0]), "+f"(d[1]), "+f"(d[2]), "+f"(d[3])
        : "r"(a[0]), "r"(a[1]), "r"(a[2]), "r"(a[3]), "r"(b[0]), "r"(b[1]));
}
__device__ __forceinline__ void ldsm4(unsigned* r, const __nv_bfloat16* p) {
    unsigned addr = (unsigned)__cvta_generic_to_shared(p);
    asm volatile("ldmatrix.sync.aligned.m8n8.x4.shared.b16 {%0,%1,%2,%3}, [%4];"
                 : "=r"(r[0]), "=r"(r[1]), "=r"(r[2]), "=r"(r[3]) : "r"(addr));
}
__device__ __forceinline__ float2 bf2f(unsigned u) {
    __nv_bfloat162 b = *(__nv_bfloat162*)&u;
    return __bfloat1622float2(b);
}

// ============ KG: gather obs -> bf16 contact [B x 320] ============
__global__ __launch_bounds__(256) void kg_gather(const float* __restrict__ obs) {
    int idx = blockIdx.x * 256 + threadIdx.x;
    int row = idx / 160, p = idx % 160;
    int k0 = p * 2;
    float v0 = 0.f, v1 = 0.f;
    if (k0 < 308) {
        int c0 = (k0 < 224) ? 45 + k0 : 68 + k0;
        v0 = obs[(size_t)row * 376 + c0];
    }
    if (k0 + 1 < 308) {
        int c1 = (k0 + 1 < 224) ? 46 + k0 : 69 + k0;
        v1 = obs[(size_t)row * 376 + c1];
    }
    *(__nv_bfloat162*)&g_Cb[(size_t)row * 320 + k0] = __floats2bfloat162_rn(v0, v1);
}

// ============ K0: fold precompute + bf16 weight conversion ============
__global__ __launch_bounds__(256) void k0_fold(
    const float* __restrict__ Wr, const float* __restrict__ br,
    const float* __restrict__ Win, const float* __restrict__ bin_,
    const float* __restrict__ Wout, const float* __restrict__ bout,
    const float* __restrict__ W2, const float* __restrict__ W1) {
    __shared__ float QW[64 * 12];
    __shared__ float qsS[64];
    const int tid = threadIdx.x, bx = blockIdx.x;

    if (bx == 0) {
        for (int idx = tid; idx < 704; idx += 256) {
            int e = idx / 11, t = idx % 11;
            float acc = 0.f;
            for (int d = 0; d < 64; ++d) acc = fmaf(Win[e * 64 + d], Wr[d * 11 + t], acc);
            QW[e * 12 + t] = acc;
        }
        for (int idx = tid; idx < 64; idx += 256) {
            float acc = bin_[idx];
            for (int d = 0; d < 64; ++d) acc = fmaf(Win[idx * 64 + d], br[d], acc);
            qsS[idx] = acc;
        }
        __syncthreads();
        for (int idx = tid; idx < 2816; idx += 256) {
            int hj = idx / 11, t = idx % 11;
            int h = hj >> 6, j = hj & 63;
            float acc = 0.f;
            for (int e = 0; e < 16; ++e) {
                int x = h * 16 + e;
                acc = fmaf(Win[4096 + x * 64 + j], QW[x * 12 + t], acc);
            }
            g_A1T[t * 256 + hj] = acc;
        }
        for (int idx = tid; idx < 256; idx += 256) {
            int h = idx >> 6, j = idx & 63;
            float acc = 0.f;
            for (int e = 0; e < 16; ++e) {
                int x = h * 16 + e;
                acc = fmaf(Win[4096 + x * 64 + j], qsS[x], acc);
            }
            g_c1[idx] = acc;
        }
        for (int idx = tid; idx < 64; idx += 256) {
            float acc = bout[idx];
            for (int d = 0; d < 64; ++d) acc = fmaf(Wout[idx * 64 + d], bin_[128 + d], acc);
            g_cb[idx] = acc;
        }
    }
    for (int idx = tid; idx < 2048; idx += 256) {
        int e = bx * 8 + (idx >> 8);
        int hj = idx & 255, h = hj >> 6, j = hj & 63;
        float acc = 0.f;
        for (int d = 0; d < 16; ++d)
            acc = fmaf(Wout[e * 64 + h * 16 + d], Win[8192 + (h * 16 + d) * 64 + j], acc);
        g_Gb[e * 256 + hj] = __float2bfloat16(acc);
    }
    for (int idx = bx * 16384 + tid; idx < (bx + 1) * 16384; idx += 256)
        g_W2b[idx] = __float2bfloat16(W2[idx]);
    for (int idx = bx * 10240 + tid; idx < (bx + 1) * 10240; idx += 256) {
        int n = idx / 320, k = idx % 320;
        g_W1b[idx] = __float2bfloat16((k < 308) ? W1[n * 308 + k] : 0.f);
    }
}

// ============ bf16 GEMM 128x128, BK=32, 3-stage ring, ldmatrix, 3 CTA/SM ============
#define GEMM_SMEM_BYTES (3 * 128 * 40 * 2 * 2)

template <int KT, int KROW, bool RELU, int LDC>
__global__ __launch_bounds__(256, 3) void gemm_bf16(
    const __nv_bfloat16* __restrict__ A, const __nv_bfloat16* __restrict__ W,
    const float* __restrict__ bias, __nv_bfloat16* __restrict__ C) {
    extern __shared__ __nv_bfloat16 smb[];
    __nv_bfloat16* As = smb;                 // [3][128][40]
    __nv_bfloat16* Bs = smb + 3 * 128 * 40;  // [3][128][40]
    const int tid = threadIdx.x;
    const int lane = tid & 31, w = tid >> 5;
    const int row0 = blockIdx.x * 128, n0 = blockIdx.y * 128;
    const int wm = (w & 1) * 64, wn = (w >> 1) * 32;
    const int g = lane >> 2, tig = lane & 3;
    const int lr = lane & 7, q = lane >> 3;
    const int arow = lr + ((q & 1) << 3);
    const int akof = (q >> 1) * 8;
    const int brow = lr + ((q >> 1) << 3);
    const int bkof = (q & 1) * 8;

    float acc[4][4][4] = {};

    auto loadTile = [&](int s, int kt) {
        const int kb = kt * 32;
#pragma unroll
        for (int l = 0; l < 2; ++l) {
            int idx = tid + l * 256;
            int r = idx >> 2, c = (idx & 3) * 8;
            cp16((unsigned)__cvta_generic_to_shared(&As[(s * 128 + r) * 40 + c]),
                 A + (size_t)(row0 + r) * KROW + kb + c);
            cp16((unsigned)__cvta_generic_to_shared(&Bs[(s * 128 + r) * 40 + c]),
                 W + (size_t)(n0 + r) * KROW + kb + c);
        }
    };

    loadTile(0, 0);
    CP_COMMIT;
    loadTile(1, 1);
    CP_COMMIT;

    int s = 0;
    for (int kt = 0; kt < KT; ++kt) {
        if (kt + 1 < KT) { CP_WAIT1; } else { CP_WAIT0; }
        __syncthreads();
        if (kt + 2 < KT) {
            int s2 = s + 2;
            if (s2 >= 3) s2 -= 3;
            loadTile(s2, kt + 2);
            CP_COMMIT;
        }
#pragma unroll
        for (int km = 0; km < 2; ++km) {
            const int kf = km * 16;
            unsigned a[4][4], bb[2][4];
#pragma unroll
            for (int mt = 0; mt < 4; ++mt)
                ldsm4(a[mt], &As[(s * 128 + wm + mt * 16 + arow) * 40 + kf + akof]);
#pragma unroll
            for (int p = 0; p < 2; ++p)
                ldsm4(bb[p], &Bs[(s * 128 + wn + p * 16 + brow) * 40 + kf + bkof]);
#pragma unroll
            for (int mt = 0; mt < 4; ++mt)
#pragma unroll
                for (int nt = 0; nt < 4; ++nt)
                    mma16(acc[mt][nt], a[mt], &bb[nt >> 1][(nt & 1) * 2]);
        }
        if (++s == 3) s = 0;
    }

#pragma unroll
    for (int mt = 0; mt < 4; ++mt) {
#pragma unroll
        for (int nt = 0; nt < 4; ++nt) {
            int row = row0 + wm + mt * 16 + g;
            int col = n0 + wn + nt * 8 + 2 * tig;
            float b0 = __ldg(bias + col), b1 = __ldg(bias + col + 1);
            float v0 = acc[mt][nt][0] + b0, v1 = acc[mt][nt][1] + b1;
            float v2 = acc[mt][nt][2] + b0, v3 = acc[mt][nt][3] + b1;
            if (RELU) {
                v0 = fmaxf(v0, 0.f); v1 = fmaxf(v1, 0.f);
                v2 = fmaxf(v2, 0.f); v3 = fmaxf(v3, 0.f);
            }
            *(__nv_bfloat162*)&C[(size_t)row * LDC + col] =
                __floats2bfloat162_rn(v0, v1);
            *(__nv_bfloat162*)&C[(size_t)(row + 8) * LDC + col] =
                __floats2bfloat162_rn(v2, v3);
        }
    }
}

// ============ K3a: bf16 toks, block-coop s1, scores, softmax, entropy, wtok ============
#define K3A_SMEM_FLOATS 9664
#define K3A_SMEM_BYTES (K3A_SMEM_FLOATS * 4)

__global__ __launch_bounds__(256) void k3a_attn(const float* __restrict__ obs,
                                                float* __restrict__ out_ent) {
    extern __shared__ float sm[];
    __nv_bfloat16* toksb = (__nv_bfloat16*)sm;
    float* s1S   = sm + 4608;
    float* rootS = s1S + 4352;
    float* attnS = rootS + 192;

    const int tid = threadIdx.x;
    const int lane = tid & 31, w = tid >> 5;
    const int row0 = blockIdx.x * 16;

    {
        const __nv_bfloat16* src = g_tokb + (size_t)row0 * 512;
#pragma unroll
        for (int l = 0; l < 4; ++l) {
            int idx = (tid + l * 256) * 8;
            int r = idx >> 9, c = idx & 511;
            cp16((unsigned)__cvta_generic_to_shared(
                     &toksb[r * 576 + (c >> 6) * 72 + (c & 63)]),
                 src + (size_t)r * 512 + c);
        }
    }
    CP_COMMIT;
    for (int idx = tid; idx < 176; idx += 256) {
        int r = idx / 11, j = idx % 11;
        int col = (j < 5) ? j : (17 + j);
        rootS[r * 12 + j] = obs[(size_t)(row0 + r) * 376 + col];
    }
    float a1[11];
#pragma unroll
    for (int t = 0; t < 11; ++t) a1[t] = g_A1T[t * 256 + tid];
    const float c1v = g_c1[tid];
    CP_WAIT0;
    __syncthreads();

    {
        const int dst = (tid >> 6) * 68 + (tid & 63);
#pragma unroll
        for (int r = 0; r < 16; ++r) {
            float acc = c1v;
#pragma unroll
            for (int t = 0; t < 11; ++t) acc = fmaf(rootS[r * 12 + t], a1[t], acc);
            s1S[r * 272 + dst] = acc;
        }
    }
    __syncthreads();

    const int h = lane >> 3, t = lane & 7;
    const int hh = lane >> 3;
    const int jb = (lane & 7) * 8;
#pragma unroll
    for (int rr = 0; rr < 2; ++rr) {
        const int r = w * 2 + rr;
        const size_t row = (size_t)row0 + r;
        float4 sv = {0.f, 0.f, 0.f, 0.f};
        const float* s1p = &s1S[r * 272 + h * 68];
        const uint4* tpv = (const uint4*)(toksb + r * 576 + t * 72);
#pragma unroll
        for (int j8 = 0; j8 < 8; ++j8) {
            uint4 u = tpv[j8];
            float2 t0 = bf2f(u.x), t1 = bf2f(u.y), t2 = bf2f(u.z), t3 = bf2f(u.w);
            float4 a0 = *(const float4*)(s1p + 8 * j8);
            float4 a1_ = *(const float4*)(s1p + 8 * j8 + 4);
            sv.x = fmaf(a0.x, t0.x, sv.x);
            sv.y = fmaf(a0.y, t0.y, sv.y);
            sv.z = fmaf(a0.z, t1.x, sv.z);
            sv.w = fmaf(a0.w, t1.y, sv.w);
            sv.x = fmaf(a1_.x, t2.x, sv.x);
            sv.y = fmaf(a1_.y, t2.y, sv.y);
            sv.z = fmaf(a1_.z, t3.x, sv.z);
            sv.w = fmaf(a1_.w, t3.y, sv.w);
        }
        float s = (sv.x + sv.y + sv.z + sv.w) * 0.25f;
        float m = s;
        m = fmaxf(m, __shfl_xor_sync(0xffffffffu, m, 1, 8));
        m = fmaxf(m, __shfl_xor_sync(0xffffffffu, m, 2, 8));
        m = fmaxf(m, __shfl_xor_sync(0xffffffffu, m, 4, 8));
        float ex = expf(s - m);
        float den = ex;
        den += __shfl_xor_sync(0xffffffffu, den, 1, 8);
        den += __shfl_xor_sync(0xffffffffu, den, 2, 8);
        den += __shfl_xor_sync(0xffffffffu, den, 4, 8);
        float a = ex / den;
        attnS[r * 32 + lane] = a;
        float ah = a;
        ah += __shfl_xor_sync(0xffffffffu, ah, 8);
        ah += __shfl_xor_sync(0xffffffffu, ah, 16);
        float aw = fmaxf(ah * 0.25f, 1e-8f);
        float term = -aw * logf(aw);
        term += __shfl_xor_sync(0xffffffffu, term, 1, 8);
        term += __shfl_xor_sync(0xffffffffu, term, 2, 8);
        term += __shfl_xor_sync(0xffffffffu, term, 4, 8);
        if (lane == 0) out_ent[row] = term;
        __syncwarp();
        float av[8];
#pragma unroll
        for (int tt = 0; tt < 8; ++tt) av[tt] = attnS[r * 32 + hh * 8 + tt];
        float4 acc0 = {0.f, 0.f, 0.f, 0.f}, acc1 = {0.f, 0.f, 0.f, 0.f};
        const __nv_bfloat16* tb = toksb + r * 576 + jb;
#pragma unroll
        for (int tt = 0; tt < 8; ++tt) {
            uint4 u = *(const uint4*)(tb + tt * 72);
            float2 t0 = bf2f(u.x), t1 = bf2f(u.y), t2 = bf2f(u.z), t3 = bf2f(u.w);
            float av_ = av[tt];
            acc0.x = fmaf(av_, t0.x, acc0.x);
            acc0.y = fmaf(av_, t0.y, acc0.y);
            acc0.z = fmaf(av_, t1.x, acc0.z);
            acc0.w = fmaf(av_, t1.y, acc0.w);
            acc1.x = fmaf(av_, t2.x, acc1.x);
            acc1.y = fmaf(av_, t2.y, acc1.y);
            acc1.z = fmaf(av_, t3.x, acc1.z);
            acc1.w = fmaf(av_, t3.y, acc1.w);
        }
        __nv_bfloat162 pk[4];
        pk[0] = __floats2bfloat162_rn(acc0.x, acc0.y);
        pk[1] = __floats2bfloat162_rn(acc0.z, acc0.w);
        pk[2] = __floats2bfloat162_rn(acc1.x, acc1.y);
        pk[3] = __floats2bfloat162_rn(acc1.z, acc1.w);
        *(uint4*)&g_wtokb[row * 256 + lane * 8] = *(uint4*)pk;
    }
}

// ============ K4: bf16 GEMM y = wtok@G^T + cb, + remb + LN + head ============
#define K4_SMEM_FLOATS 13184
#define K4_SMEM_BYTES (K4_SMEM_FLOATS * 4)

__global__ __launch_bounds__(256) void k4_out_ln_head(
    const float* __restrict__ obs,
    const float* __restrict__ Wr, const float* __restrict__ br,
    const float* __restrict__ gamma, const float* __restrict__ beta,
    const float* __restrict__ Wh1, const float* __restrict__ bh1,
    const float* __restrict__ Wh2, const float* __restrict__ bh2,
    float* __restrict__ out_ctx) {
    extern __shared__ float sm[];
    __nv_bfloat16* Asb = (__nv_bfloat16*)sm;
    __nv_bfloat16* Bsb = Asb + 2 * 128 * 24;
    float* ys = sm;
    float* Wh1S  = sm + 8704;
    float* WrS   = sm + 10880;
    float* rootS = sm + 11648;

    const int tid = threadIdx.x;
    const int lane = tid & 31, w = tid >> 5;
    const int row0 = blockIdx.x * 128;
    const int wm = (w & 3) * 32, wn = (w >> 2) * 32;
    const int g = lane >> 2, tig = lane & 3;

    float acc[2][4][4] = {};

    auto loadTile = [&](int s, int kt) {
        const int kb = kt * 16;
        {
            int r = tid >> 1, off = (tid & 1) * 8;
            cp16((unsigned)__cvta_generic_to_shared(&Asb[(s * 128 + r) * 24 + off]),
                 g_wtokb + (size_t)(row0 + r) * 256 + kb + off);
        }
        if (tid < 128) {
            int n = tid >> 1, off = (tid & 1) * 8;
            cp16((unsigned)__cvta_generic_to_shared(&Bsb[(s * 64 + n) * 24 + off]),
                 g_Gb + (size_t)n * 256 + kb + off);
        }
    };

    loadTile(0, 0);
    CP_COMMIT;
    for (int kt = 0; kt < 16; ++kt) {
        CP_WAIT0;
        __syncthreads();
        if (kt + 1 < 16) {
            loadTile((kt + 1) & 1, kt + 1);
            CP_COMMIT;
        }
        const int s = kt & 1;
        unsigned a[2][4], b[4][2];
#pragma unroll
        for (int mt = 0; mt < 2; ++mt) {
            int r = wm + mt * 16 + g;
            a[mt][0] = *(const unsigned*)&Asb[(s * 128 + r) * 24 + tig * 2];
            a[mt][1] = *(const unsigned*)&Asb[(s * 128 + r + 8) * 24 + tig * 2];
            a[mt][2] = *(const unsigned*)&Asb[(s * 128 + r) * 24 + tig * 2 + 8];
            a[mt][3] = *(const unsigned*)&Asb[(s * 128 + r + 8) * 24 + tig * 2 + 8];
        }
#pragma unroll
        for (int nt = 0; nt < 4; ++nt) {
            int n = wn + nt * 8 + g;
            b[nt][0] = *(const unsigned*)&Bsb[(s * 64 + n) * 24 + tig * 2];
            b[nt][1] = *(const unsigned*)&Bsb[(s * 64 + n) * 24 + tig * 2 + 8];
        }
#pragma unroll
        for (int mt = 0; mt < 2; ++mt)
#pragma unroll
            for (int nt = 0; nt < 4; ++nt) mma16(acc[mt][nt], a[mt], b[nt]);
    }
    __syncthreads();

#pragma unroll
    for (int mt = 0; mt < 2; ++mt) {
#pragma unroll
        for (int nt = 0; nt < 4; ++nt) {
            int r = wm + mt * 16 + g;
            int col = wn + nt * 8 + 2 * tig;
            float c0 = g_cb[col], c1 = g_cb[col + 1];
            ys[r * 68 + col]           = acc[mt][nt][0] + c0;
            ys[r * 68 + col + 1]       = acc[mt][nt][1] + c1;
            ys[(r + 8) * 68 + col]     = acc[mt][nt][2] + c0;
            ys[(r + 8) * 68 + col + 1] = acc[mt][nt][3] + c1;
        }
    }
    for (int idx = tid; idx < 2048; idx += 256)
        Wh1S[(idx >> 6) * 68 + (idx & 63)] = Wh1[idx];
    for (int idx = tid; idx < 704; idx += 256)
        WrS[(idx / 11) * 12 + (idx % 11)] = Wr[idx];
    for (int idx = tid; idx < 1408; idx += 256) {
        int r = idx / 11, j = idx % 11;
        int col = (j < 5) ? j : (17 + j);
        rootS[r * 12 + j] = obs[(size_t)(row0 + r) * 376 + col];
    }
    __syncthreads();

    const float gm0 = gamma[lane], gm1 = gamma[lane + 32];
    const float bt0 = beta[lane],  bt1 = beta[lane + 32];
    const float br0 = br[lane],    br1 = br[lane + 32];
    const float bh1v = bh1[lane], wh2v = Wh2[lane], bh2v = bh2[0];

#pragma unroll 2
    for (int rr = 0; rr < 16; ++rr) {
        const int r = w * 16 + rr;
        const size_t row = (size_t)row0 + r;
        float e0 = br0, e1 = br1;
#pragma unroll
        for (int j = 0; j < 11; ++j) {
            float rv = rootS[r * 12 + j];
            e0 = fmaf(rv, WrS[lane * 12 + j], e0);
            e1 = fmaf(rv, WrS[(lane + 32) * 12 + j], e1);
        }
        float x0 = ys[r * 68 + lane] + e0;
        float x1 = ys[r * 68 + lane + 32] + e1;
        float ssum = x0 + x1;
#pragma unroll
        for (int o = 16; o > 0; o >>= 1) ssum += __shfl_xor_sync(0xffffffffu, ssum, o);
        float mu = ssum * (1.f / 64.f);
        float d0 = x0 - mu, d1 = x1 - mu;
        float vs = d0 * d0 + d1 * d1;
#pragma unroll
        for (int o = 16; o > 0; o >>= 1) vs += __shfl_xor_sync(0xffffffffu, vs, o);
        float inv = rsqrtf(vs * (1.f / 64.f) + 1e-5f);
        float c0 = fmaf(gm0, d0 * inv, bt0);
        float c1 = fmaf(gm1, d1 * inv, bt1);
        out_ctx[row * 64 + lane] = c0;
        out_ctx[row * 64 + lane + 32] = c1;
        ys[r * 68 + lane] = c0;
        ys[r * 68 + lane + 32] = c1;
        __syncwarp();
        float4 hv = {0.f, 0.f, 0.f, 0.f};
#pragma unroll
        for (int d4 = 0; d4 < 16; ++d4) {
            float4 yv = *(const float4*)&ys[r * 68 + 4 * d4];
            float4 wv = *(const float4*)&Wh1S[lane * 68 + 4 * d4];
            hv.x = fmaf(yv.x, wv.x, hv.x);
            hv.y = fmaf(yv.y, wv.y, hv.y);
            hv.z = fmaf(yv.z, wv.z, hv.z);
            hv.w = fmaf(yv.w, wv.w, hv.w);
        }
        float v = fmaxf(hv.x + hv.y + hv.z + hv.w + bh1v, 0.f) * wh2v;
#pragma unroll
        for (int o = 16; o > 0; o >>= 1) v += __shfl_xor_sync(0xffffffffu, v, o);
        if (lane == 0) g_raw[row] = v + bh2v;
        __syncwarp();
    }
}

// ================= batch reductions =================
__global__ void k_reduce_raw() {
    __shared__ float s[256];
    int tid = threadIdx.x;
    int i = blockIdx.x * 512 + tid;
    s[tid] = g_raw[i] + g_raw[i + 256];
    __syncthreads();
    for (int o = 128; o > 0; o >>= 1) {
        if (tid < o) s[tid] += s[tid + o];
        __syncthreads();
    }
    if (tid == 0) g_part[blockIdx.x] = s[0];
}
__global__ void k_finish_raw() {
    __shared__ float s[256];
    int tid = threadIdx.x;
    s[tid] = g_part[tid];
    __syncthreads();
    for (int o = 128; o > 0; o >>= 1) {
        if (tid < o) s[tid] += s[tid + o];
        __syncthreads();
    }
    if (tid == 0) g_scalars[0] = s[0] * (1.f / (float)BATCH);
}
__global__ void k_reduce_lw() {
    __shared__ float s[256];
    int tid = threadIdx.x;
    float mean = g_scalars[0];
    int i = blockIdx.x * 512 + tid;
    s[tid] = expf(0.5f * tanhf(g_raw[i] - mean)) +
             expf(0.5f * tanhf(g_raw[i + 256] - mean));
    __syncthreads();
    for (int o = 128; o > 0; o >>= 1) {
        if (tid < o) s[tid] += s[tid + o];
        __syncthreads();
    }
    if (tid == 0) g_part[blockIdx.x] = s[0];
}
__global__ void k_finish_lw() {
    __shared__ float s[256];
    int tid = threadIdx.x;
    s[tid] = g_part[tid];
    __syncthreads();
    for (int o = 128; o > 0; o >>= 1) {
        if (tid < o) s[tid] += s[tid + o];
        __syncthreads();
    }
    if (tid == 0) g_scalars[1] = fmaxf(s[0] * (1.f / (float)BATCH), 1e-6f);
}
__global__ void k_write_lw(float* __restrict__ out_lw) {
    int i = blockIdx.x * 256 + threadIdx.x;
    float lw = expf(0.5f * tanhf(g_raw[i] - g_scalars[0]));
    out_lw[i] = lw / g_scalars[1];
}

// =====================================================================
extern "C" void kernel_launch(void* const* d_in, const int* in_sizes, int n_in,
                              void* d_out, int out_size) {
    const float* obs   = (const float*)d_in[0];
    const float* W1    = (const float*)d_in[1];
    const float* b1    = (const float*)d_in[2];
    const float* W2    = (const float*)d_in[3];
    const float* b2    = (const float*)d_in[4];
    const float* Wr    = (const float*)d_in[5];
    const float* br    = (const float*)d_in[6];
    const float* Win   = (const float*)d_in[7];
    const float* bin_  = (const float*)d_in[8];
    const float* Wout  = (const float*)d_in[9];
    const float* bout  = (const float*)d_in[10];
    const float* gamma = (const float*)d_in[11];
    const float* beta  = (const float*)d_in[12];
    const float* Wh1   = (const float*)d_in[13];
    const float* bh1   = (const float*)d_in[14];
    const float* Wh2   = (const float*)d_in[15];
    const float* bh2   = (const float*)d_in[16];

    float* out     = (float*)d_out;
    float* out_ctx = out;
    float* out_lw  = out + (size_t)BATCH * 64;
    float* out_ent = out_lw + BATCH;

    __nv_bfloat16* d_Cb;  cudaGetSymbolAddress((void**)&d_Cb, g_Cb);
    __nv_bfloat16* d_Hb;  cudaGetSymbolAddress((void**)&d_Hb, g_Hb);
    __nv_bfloat16* d_W1b; cudaGetSymbolAddress((void**)&d_W1b, g_W1b);
    __nv_bfloat16* d_W2b; cudaGetSymbolAddress((void**)&d_W2b, g_W2b);
    __nv_bfloat16* d_tok; cudaGetSymbolAddress((void**)&d_tok, g_tokb);

    cudaFuncSetAttribute((const void*)gemm_bf16<10, 320, true, 256>,
                         cudaFuncAttributeMaxDynamicSharedMemorySize, GEMM_SMEM_BYTES);
    cudaFuncSetAttribute((const void*)gemm_bf16<8, 256, false, 512>,
                         cudaFuncAttributeMaxDynamicSharedMemorySize, GEMM_SMEM_BYTES);
    cudaFuncSetAttribute(k3a_attn, cudaFuncAttributeMaxDynamicSharedMemorySize,
                         K3A_SMEM_BYTES);
    cudaFuncSetAttribute(k4_out_ln_head, cudaFuncAttributeMaxDynamicSharedMemorySize,
                         K4_SMEM_BYTES);

    k0_fold<<<8, 256>>>(Wr, br, Win, bin_, Wout, bout, W2, W1);
    kg_gather<<<BATCH * 160 / 256, 256>>>(obs);
    gemm_bf16<10, 320, true, 256><<<dim3(BATCH / 128, 2), 256, GEMM_SMEM_BYTES>>>(
        d_Cb, d_W1b, b1, d_Hb);
    gemm_bf16<8, 256, false, 512><<<dim3(BATCH / 128, 4), 256, GEMM_SMEM_BYTES>>>(
        d_Hb, d_W2b, b2, d_tok);
    k3a_attn<<<BATCH / 16, 256, K3A_SMEM_BYTES>>>(obs, out_ent);
    k4_out_ln_head<<<BATCH / 128, 256, K4_SMEM_BYTES>>>(
        obs, Wr, br, gamma, beta, Wh1, bh1, Wh2, bh2, out_ctx);
    k_reduce_raw<<<256, 256>>>();
    k_finish_raw<<<1, 256>>>();
    k_reduce_lw<<<256, 256>>>();
    k_finish_lw<<<1, 256>>>();
    k_write_lw<<<BATCH / 256, 256>>>(out_lw);
}

// round 16
// speedup vs baseline: 1.0856x; 1.0856x over previous
#include <cuda_runtime.h>
#include <cuda_bf16.h>
#include <math.h>

#define BATCH 131072

__device__ __nv_bfloat16 g_Cb[(size_t)BATCH * 320];
__device__ __nv_bfloat16 g_Hb[(size_t)BATCH * 256];
__device__ __nv_bfloat16 g_tokb[(size_t)BATCH * 512];
__device__ __nv_bfloat16 g_wtokb[(size_t)BATCH * 256];
__device__ float g_raw[BATCH];
__device__ float g_part[256];
__device__ float g_scalars[2];
__device__ float g_A1T[12 * 256];
__device__ float g_c1[256];
__device__ __nv_bfloat16 g_Gb[64 * 256];
__device__ float g_cb[64];
__device__ __nv_bfloat16 g_W2b[512 * 256];
__device__ __nv_bfloat16 g_W1b[256 * 320];

// ---------------- helpers ----------------
__device__ __forceinline__ void cp16(unsigned dst, const void* src) {
    asm volatile("cp.async.cg.shared.global [%0], [%1], 16;" ::
                 "r"(dst), "l"(src));
}
#define CP_COMMIT asm volatile("cp.async.commit_group;")
#define CP_WAIT0  asm volatile("cp.async.wait_group 0;")
#define CP_WAIT1  asm volatile("cp.async.wait_group 1;")
#define CP_WAIT2  asm volatile("cp.async.wait_group 2;")

__device__ __forceinline__ void mma16(float* d, const unsigned* a, const unsigned* b) {
    asm volatile(
        "mma.sync.aligned.m16n8k16.row.col.f32.bf16.bf16.f32 "
        "{%0,%1,%2,%3}, {%4,%5,%6,%7}, {%8,%9}, {%0,%1,%2,%3};"
        : "+f"(d[0]), "+f"(d[1]), "+f"(d[2]), "+f"(d[3])
        : "r"(a[0]), "r"(a[1]), "r"(a[2]), "r"(a[3]), "r"(b[0]), "r"(b[1]));
}
__device__ __forceinline__ void ldsm4(unsigned* r, const __nv_bfloat16* p) {
    unsigned addr = (unsigned)__cvta_generic_to_shared(p);
    asm volatile("ldmatrix.sync.aligned.m8n8.x4.shared.b16 {%0,%1,%2,%3}, [%4];"
                 : "=r"(r[0]), "=r"(r[1]), "=r"(r[2]), "=r"(r[3]) : "r"(addr));
}
__device__ __forceinline__ float2 bf2f(unsigned u) {
    __nv_bfloat162 b = *(__nv_bfloat162*)&u;
    return __bfloat1622float2(b);
}

// ============ KG: gather obs -> bf16 contact [B x 320] ============
__global__ __launch_bounds__(256) void kg_gather(const float* __restrict__ obs) {
    int idx = blockIdx.x * 256 + threadIdx.x;
    int row = idx / 160, p = idx % 160;
    int k0 = p * 2;
    float v0 = 0.f, v1 = 0.f;
    if (k0 < 308) {
        int c0 = (k0 < 224) ? 45 + k0 : 68 + k0;
        v0 = obs[(size_t)row * 376 + c0];
    }
    if (k0 + 1 < 308) {
        int c1 = (k0 + 1 < 224) ? 46 + k0 : 69 + k0;
        v1 = obs[(size_t)row * 376 + c1];
    }
    *(__nv_bfloat162*)&g_Cb[(size_t)row * 320 + k0] = __floats2bfloat162_rn(v0, v1);
}

// ============ K0: fold precompute + bf16 weight conversion ============
__global__ __launch_bounds__(256) void k0_fold(
    const float* __restrict__ Wr, const float* __restrict__ br,
    const float* __restrict__ Win, const float* __restrict__ bin_,
    const float* __restrict__ Wout, const float* __restrict__ bout,
    const float* __restrict__ W2, const float* __restrict__ W1) {
    __shared__ float QW[64 * 12];
    __shared__ float qsS[64];
    const int tid = threadIdx.x, bx = blockIdx.x;

    if (bx == 0) {
        for (int idx = tid; idx < 704; idx += 256) {
            int e = idx / 11, t = idx % 11;
            float acc = 0.f;
            for (int d = 0; d < 64; ++d) acc = fmaf(Win[e * 64 + d], Wr[d * 11 + t], acc);
            QW[e * 12 + t] = acc;
        }
        for (int idx = tid; idx < 64; idx += 256) {
            float acc = bin_[idx];
            for (int d = 0; d < 64; ++d) acc = fmaf(Win[idx * 64 + d], br[d], acc);
            qsS[idx] = acc;
        }
        __syncthreads();
        for (int idx = tid; idx < 2816; idx += 256) {
            int hj = idx / 11, t = idx % 11;
            int h = hj >> 6, j = hj & 63;
            float acc = 0.f;
            for (int e = 0; e < 16; ++e) {
                int x = h * 16 + e;
                acc = fmaf(Win[4096 + x * 64 + j], QW[x * 12 + t], acc);
            }
            g_A1T[t * 256 + hj] = acc;
        }
        for (int idx = tid; idx < 256; idx += 256) {
            int h = idx >> 6, j = idx & 63;
            float acc = 0.f;
            for (int e = 0; e < 16; ++e) {
                int x = h * 16 + e;
                acc = fmaf(Win[4096 + x * 64 + j], qsS[x], acc);
            }
            g_c1[idx] = acc;
        }
        for (int idx = tid; idx < 64; idx += 256) {
            float acc = bout[idx];
            for (int d = 0; d < 64; ++d) acc = fmaf(Wout[idx * 64 + d], bin_[128 + d], acc);
            g_cb[idx] = acc;
        }
    }
    for (int idx = tid; idx < 2048; idx += 256) {
        int e = bx * 8 + (idx >> 8);
        int hj = idx & 255, h = hj >> 6, j = hj & 63;
        float acc = 0.f;
        for (int d = 0; d < 16; ++d)
            acc = fmaf(Wout[e * 64 + h * 16 + d], Win[8192 + (h * 16 + d) * 64 + j], acc);
        g_Gb[e * 256 + hj] = __float2bfloat16(acc);
    }
    for (int idx = bx * 16384 + tid; idx < (bx + 1) * 16384; idx += 256)
        g_W2b[idx] = __float2bfloat16(W2[idx]);
    for (int idx = bx * 10240 + tid; idx < (bx + 1) * 10240; idx += 256) {
        int n = idx / 320, k = idx % 320;
        g_W1b[idx] = __float2bfloat16((k < 308) ? W1[n * 308 + k] : 0.f);
    }
}

// ============ bf16 GEMM 128x128, BK=32, 4-stage cp.async ring, ldmatrix ============
#define GEMM_SMEM_BYTES (4 * 128 * 40 * 2 * 2)

template <int KT, int KROW, bool RELU, int LDC>
__global__ __launch_bounds__(256) void gemm_bf16(
    const __nv_bfloat16* __restrict__ A, const __nv_bfloat16* __restrict__ W,
    const float* __restrict__ bias, __nv_bfloat16* __restrict__ C) {
    extern __shared__ __nv_bfloat16 smb[];
    __nv_bfloat16* As = smb;                 // [4][128][40]
    __nv_bfloat16* Bs = smb + 4 * 128 * 40;  // [4][128][40]
    const int tid = threadIdx.x;
    const int lane = tid & 31, w = tid >> 5;
    const int row0 = blockIdx.x * 128, n0 = blockIdx.y * 128;
    const int wm = (w & 1) * 64, wn = (w >> 1) * 32;
    const int g = lane >> 2, tig = lane & 3;
    const int lr = lane & 7, q = lane >> 3;
    const int arow = lr + ((q & 1) << 3);
    const int akof = (q >> 1) * 8;
    const int brow = lr + ((q >> 1) << 3);
    const int bkof = (q & 1) * 8;

    float acc[4][4][4] = {};

    auto loadTile = [&](int s, int kt) {
        const int kb = kt * 32;
#pragma unroll
        for (int l = 0; l < 2; ++l) {
            int idx = tid + l * 256;
            int r = idx >> 2, c = (idx & 3) * 8;
            cp16((unsigned)__cvta_generic_to_shared(&As[(s * 128 + r) * 40 + c]),
                 A + (size_t)(row0 + r) * KROW + kb + c);
            cp16((unsigned)__cvta_generic_to_shared(&Bs[(s * 128 + r) * 40 + c]),
                 W + (size_t)(n0 + r) * KROW + kb + c);
        }
    };

    loadTile(0, 0);
    CP_COMMIT;
    loadTile(1, 1);
    CP_COMMIT;
    loadTile(2, 2);
    CP_COMMIT;

    int s = 0;
    for (int kt = 0; kt < KT; ++kt) {
        if (kt + 2 < KT) { CP_WAIT2; }
        else if (kt + 1 < KT) { CP_WAIT1; }
        else { CP_WAIT0; }
        __syncthreads();
        if (kt + 3 < KT) {
            loadTile((s + 3) & 3, kt + 3);
            CP_COMMIT;
        }
#pragma unroll
        for (int km = 0; km < 2; ++km) {
            const int kf = km * 16;
            unsigned a[4][4], bb[2][4];
#pragma unroll
            for (int mt = 0; mt < 4; ++mt)
                ldsm4(a[mt], &As[(s * 128 + wm + mt * 16 + arow) * 40 + kf + akof]);
#pragma unroll
            for (int p = 0; p < 2; ++p)
                ldsm4(bb[p], &Bs[(s * 128 + wn + p * 16 + brow) * 40 + kf + bkof]);
#pragma unroll
            for (int mt = 0; mt < 4; ++mt)
#pragma unroll
                for (int nt = 0; nt < 4; ++nt)
                    mma16(acc[mt][nt], a[mt], &bb[nt >> 1][(nt & 1) * 2]);
        }
        s = (s + 1) & 3;
    }

#pragma unroll
    for (int mt = 0; mt < 4; ++mt) {
#pragma unroll
        for (int nt = 0; nt < 4; ++nt) {
            int row = row0 + wm + mt * 16 + g;
            int col = n0 + wn + nt * 8 + 2 * tig;
            float b0 = __ldg(bias + col), b1 = __ldg(bias + col + 1);
            float v0 = acc[mt][nt][0] + b0, v1 = acc[mt][nt][1] + b1;
            float v2 = acc[mt][nt][2] + b0, v3 = acc[mt][nt][3] + b1;
            if (RELU) {
                v0 = fmaxf(v0, 0.f); v1 = fmaxf(v1, 0.f);
                v2 = fmaxf(v2, 0.f); v3 = fmaxf(v3, 0.f);
            }
            *(__nv_bfloat162*)&C[(size_t)row * LDC + col] =
                __floats2bfloat162_rn(v0, v1);
            *(__nv_bfloat162*)&C[(size_t)(row + 8) * LDC + col] =
                __floats2bfloat162_rn(v2, v3);
        }
    }
}

// ============ K3a: bf16 toks, block-coop s1, scores, softmax, entropy, wtok ============
#define K3A_SMEM_FLOATS 9664
#define K3A_SMEM_BYTES (K3A_SMEM_FLOATS * 4)

__global__ __launch_bounds__(256) void k3a_attn(const float* __restrict__ obs,
                                                float* __restrict__ out_ent) {
    extern __shared__ float sm[];
    __nv_bfloat16* toksb = (__nv_bfloat16*)sm;
    float* s1S   = sm + 4608;
    float* rootS = s1S + 4352;
    float* attnS = rootS + 192;

    const int tid = threadIdx.x;
    const int lane = tid & 31, w = tid >> 5;
    const int row0 = blockIdx.x * 16;

    {
        const __nv_bfloat16* src = g_tokb + (size_t)row0 * 512;
#pragma unroll
        for (int l = 0; l < 4; ++l) {
            int idx = (tid + l * 256) * 8;
            int r = idx >> 9, c = idx & 511;
            cp16((unsigned)__cvta_generic_to_shared(
                     &toksb[r * 576 + (c >> 6) * 72 + (c & 63)]),
                 src + (size_t)r * 512 + c);
        }
    }
    CP_COMMIT;
    for (int idx = tid; idx < 176; idx += 256) {
        int r = idx / 11, j = idx % 11;
        int col = (j < 5) ? j : (17 + j);
        rootS[r * 12 + j] = obs[(size_t)(row0 + r) * 376 + col];
    }
    float a1[11];
#pragma unroll
    for (int t = 0; t < 11; ++t) a1[t] = g_A1T[t * 256 + tid];
    const float c1v = g_c1[tid];
    CP_WAIT0;
    __syncthreads();

    {
        const int dst = (tid >> 6) * 68 + (tid & 63);
#pragma unroll
        for (int r = 0; r < 16; ++r) {
            float acc = c1v;
#pragma unroll
            for (int t = 0; t < 11; ++t) acc = fmaf(rootS[r * 12 + t], a1[t], acc);
            s1S[r * 272 + dst] = acc;
        }
    }
    __syncthreads();

    const int h = lane >> 3, t = lane & 7;
    const int hh = lane >> 3;
    const int jb = (lane & 7) * 8;
#pragma unroll
    for (int rr = 0; rr < 2; ++rr) {
        const int r = w * 2 + rr;
        const size_t row = (size_t)row0 + r;
        float4 sv = {0.f, 0.f, 0.f, 0.f};
        const float* s1p = &s1S[r * 272 + h * 68];
        const uint4* tpv = (const uint4*)(toksb + r * 576 + t * 72);
#pragma unroll
        for (int j8 = 0; j8 < 8; ++j8) {
            uint4 u = tpv[j8];
            float2 t0 = bf2f(u.x), t1 = bf2f(u.y), t2 = bf2f(u.z), t3 = bf2f(u.w);
            float4 a0 = *(const float4*)(s1p + 8 * j8);
            float4 a1_ = *(const float4*)(s1p + 8 * j8 + 4);
            sv.x = fmaf(a0.x, t0.x, sv.x);
            sv.y = fmaf(a0.y, t0.y, sv.y);
            sv.z = fmaf(a0.z, t1.x, sv.z);
            sv.w = fmaf(a0.w, t1.y, sv.w);
            sv.x = fmaf(a1_.x, t2.x, sv.x);
            sv.y = fmaf(a1_.y, t2.y, sv.y);
            sv.z = fmaf(a1_.z, t3.x, sv.z);
            sv.w = fmaf(a1_.w, t3.y, sv.w);
        }
        float s = (sv.x + sv.y + sv.z + sv.w) * 0.25f;
        float m = s;
        m = fmaxf(m, __shfl_xor_sync(0xffffffffu, m, 1, 8));
        m = fmaxf(m, __shfl_xor_sync(0xffffffffu, m, 2, 8));
        m = fmaxf(m, __shfl_xor_sync(0xffffffffu, m, 4, 8));
        float ex = expf(s - m);
        float den = ex;
        den += __shfl_xor_sync(0xffffffffu, den, 1, 8);
        den += __shfl_xor_sync(0xffffffffu, den, 2, 8);
        den += __shfl_xor_sync(0xffffffffu, den, 4, 8);
        float a = ex / den;
        attnS[r * 32 + lane] = a;
        float ah = a;
        ah += __shfl_xor_sync(0xffffffffu, ah, 8);
        ah += __shfl_xor_sync(0xffffffffu, ah, 16);
        float aw = fmaxf(ah * 0.25f, 1e-8f);
        float term = -aw * logf(aw);
        term += __shfl_xor_sync(0xffffffffu, term, 1, 8);
        term += __shfl_xor_sync(0xffffffffu, term, 2, 8);
        term += __shfl_xor_sync(0xffffffffu, term, 4, 8);
        if (lane == 0) out_ent[row] = term;
        __syncwarp();
        float av[8];
#pragma unroll
        for (int tt = 0; tt < 8; ++tt) av[tt] = attnS[r * 32 + hh * 8 + tt];
        float4 acc0 = {0.f, 0.f, 0.f, 0.f}, acc1 = {0.f, 0.f, 0.f, 0.f};
        const __nv_bfloat16* tb = toksb + r * 576 + jb;
#pragma unroll
        for (int tt = 0; tt < 8; ++tt) {
            uint4 u = *(const uint4*)(tb + tt * 72);
            float2 t0 = bf2f(u.x), t1 = bf2f(u.y), t2 = bf2f(u.z), t3 = bf2f(u.w);
            float av_ = av[tt];
            acc0.x = fmaf(av_, t0.x, acc0.x);
            acc0.y = fmaf(av_, t0.y, acc0.y);
            acc0.z = fmaf(av_, t1.x, acc0.z);
            acc0.w = fmaf(av_, t1.y, acc0.w);
            acc1.x = fmaf(av_, t2.x, acc1.x);
            acc1.y = fmaf(av_, t2.y, acc1.y);
            acc1.z = fmaf(av_, t3.x, acc1.z);
            acc1.w = fmaf(av_, t3.y, acc1.w);
        }
        __nv_bfloat162 pk[4];
        pk[0] = __floats2bfloat162_rn(acc0.x, acc0.y);
        pk[1] = __floats2bfloat162_rn(acc0.z, acc0.w);
        pk[2] = __floats2bfloat162_rn(acc1.x, acc1.y);
        pk[3] = __floats2bfloat162_rn(acc1.z, acc1.w);
        *(uint4*)&g_wtokb[row * 256 + lane * 8] = *(uint4*)pk;
    }
}

// ============ K4: bf16 GEMM y = wtok@G^T + cb, + remb + LN + head ============
#define K4_SMEM_FLOATS 13184
#define K4_SMEM_BYTES (K4_SMEM_FLOATS * 4)

__global__ __launch_bounds__(256) void k4_out_ln_head(
    const float* __restrict__ obs,
    const float* __restrict__ Wr, const float* __restrict__ br,
    const float* __restrict__ gamma, const float* __restrict__ beta,
    const float* __restrict__ Wh1, const float* __restrict__ bh1,
    const float* __restrict__ Wh2, const float* __restrict__ bh2,
    float* __restrict__ out_ctx) {
    extern __shared__ float sm[];
    __nv_bfloat16* Asb = (__nv_bfloat16*)sm;
    __nv_bfloat16* Bsb = Asb + 2 * 128 * 24;
    float* ys = sm;
    float* Wh1S  = sm + 8704;
    float* WrS   = sm + 10880;
    float* rootS = sm + 11648;

    const int tid = threadIdx.x;
    const int lane = tid & 31, w = tid >> 5;
    const int row0 = blockIdx.x * 128;
    const int wm = (w & 3) * 32, wn = (w >> 2) * 32;
    const int g = lane >> 2, tig = lane & 3;

    float acc[2][4][4] = {};

    auto loadTile = [&](int s, int kt) {
        const int kb = kt * 16;
        {
            int r = tid >> 1, off = (tid & 1) * 8;
            cp16((unsigned)__cvta_generic_to_shared(&Asb[(s * 128 + r) * 24 + off]),
                 g_wtokb + (size_t)(row0 + r) * 256 + kb + off);
        }
        if (tid < 128) {
            int n = tid >> 1, off = (tid & 1) * 8;
            cp16((unsigned)__cvta_generic_to_shared(&Bsb[(s * 64 + n) * 24 + off]),
                 g_Gb + (size_t)n * 256 + kb + off);
        }
    };

    loadTile(0, 0);
    CP_COMMIT;
    for (int kt = 0; kt < 16; ++kt) {
        CP_WAIT0;
        __syncthreads();
        if (kt + 1 < 16) {
            loadTile((kt + 1) & 1, kt + 1);
            CP_COMMIT;
        }
        const int s = kt & 1;
        unsigned a[2][4], b[4][2];
#pragma unroll
        for (int mt = 0; mt < 2; ++mt) {
            int r = wm + mt * 16 + g;
            a[mt][0] = *(const unsigned*)&Asb[(s * 128 + r) * 24 + tig * 2];
            a[mt][1] = *(const unsigned*)&Asb[(s * 128 + r + 8) * 24 + tig * 2];
            a[mt][2] = *(const unsigned*)&Asb[(s * 128 + r) * 24 + tig * 2 + 8];
            a[mt][3] = *(const unsigned*)&Asb[(s * 128 + r + 8) * 24 + tig * 2 + 8];
        }
#pragma unroll
        for (int nt = 0; nt < 4; ++nt) {
            int n = wn + nt * 8 + g;
            b[nt][0] = *(const unsigned*)&Bsb[(s * 64 + n) * 24 + tig * 2];
            b[nt][1] = *(const unsigned*)&Bsb[(s * 64 + n) * 24 + tig * 2 + 8];
        }
#pragma unroll
        for (int mt = 0; mt < 2; ++mt)
#pragma unroll
            for (int nt = 0; nt < 4; ++nt) mma16(acc[mt][nt], a[mt], b[nt]);
    }
    __syncthreads();

#pragma unroll
    for (int mt = 0; mt < 2; ++mt) {
#pragma unroll
        for (int nt = 0; nt < 4; ++nt) {
            int r = wm + mt * 16 + g;
            int col = wn + nt * 8 + 2 * tig;
            float c0 = g_cb[col], c1 = g_cb[col + 1];
            ys[r * 68 + col]           = acc[mt][nt][0] + c0;
            ys[r * 68 + col + 1]       = acc[mt][nt][1] + c1;
            ys[(r + 8) * 68 + col]     = acc[mt][nt][2] + c0;
            ys[(r + 8) * 68 + col + 1] = acc[mt][nt][3] + c1;
        }
    }
    for (int idx = tid; idx < 2048; idx += 256)
        Wh1S[(idx >> 6) * 68 + (idx & 63)] = Wh1[idx];
    for (int idx = tid; idx < 704; idx += 256)
        WrS[(idx / 11) * 12 + (idx % 11)] = Wr[idx];
    for (int idx = tid; idx < 1408; idx += 256) {
        int r = idx / 11, j = idx % 11;
        int col = (j < 5) ? j : (17 + j);
        rootS[r * 12 + j] = obs[(size_t)(row0 + r) * 376 + col];
    }
    __syncthreads();

    const float gm0 = gamma[lane], gm1 = gamma[lane + 32];
    const float bt0 = beta[lane],  bt1 = beta[lane + 32];
    const float br0 = br[lane],    br1 = br[lane + 32];
    const float bh1v = bh1[lane], wh2v = Wh2[lane], bh2v = bh2[0];

#pragma unroll 2
    for (int rr = 0; rr < 16; ++rr) {
        const int r = w * 16 + rr;
        const size_t row = (size_t)row0 + r;
        float e0 = br0, e1 = br1;
#pragma unroll
        for (int j = 0; j < 11; ++j) {
            float rv = rootS[r * 12 + j];
            e0 = fmaf(rv, WrS[lane * 12 + j], e0);
            e1 = fmaf(rv, WrS[(lane + 32) * 12 + j], e1);
        }
        float x0 = ys[r * 68 + lane] + e0;
        float x1 = ys[r * 68 + lane + 32] + e1;
        float ssum = x0 + x1;
#pragma unroll
        for (int o = 16; o > 0; o >>= 1) ssum += __shfl_xor_sync(0xffffffffu, ssum, o);
        float mu = ssum * (1.f / 64.f);
        float d0 = x0 - mu, d1 = x1 - mu;
        float vs = d0 * d0 + d1 * d1;
#pragma unroll
        for (int o = 16; o > 0; o >>= 1) vs += __shfl_xor_sync(0xffffffffu, vs, o);
        float inv = rsqrtf(vs * (1.f / 64.f) + 1e-5f);
        float c0 = fmaf(gm0, d0 * inv, bt0);
        float c1 = fmaf(gm1, d1 * inv, bt1);
        out_ctx[row * 64 + lane] = c0;
        out_ctx[row * 64 + lane + 32] = c1;
        ys[r * 68 + lane] = c0;
        ys[r * 68 + lane + 32] = c1;
        __syncwarp();
        float4 hv = {0.f, 0.f, 0.f, 0.f};
#pragma unroll
        for (int d4 = 0; d4 < 16; ++d4) {
            float4 yv = *(const float4*)&ys[r * 68 + 4 * d4];
            float4 wv = *(const float4*)&Wh1S[lane * 68 + 4 * d4];
            hv.x = fmaf(yv.x, wv.x, hv.x);
            hv.y = fmaf(yv.y, wv.y, hv.y);
            hv.z = fmaf(yv.z, wv.z, hv.z);
            hv.w = fmaf(yv.w, wv.w, hv.w);
        }
        float v = fmaxf(hv.x + hv.y + hv.z + hv.w + bh1v, 0.f) * wh2v;
#pragma unroll
        for (int o = 16; o > 0; o >>= 1) v += __shfl_xor_sync(0xffffffffu, v, o);
        if (lane == 0) g_raw[row] = v + bh2v;
        __syncwarp();
    }
}

// ================= batch reductions =================
__global__ void k_reduce_raw() {
    __shared__ float s[256];
    int tid = threadIdx.x;
    int i = blockIdx.x * 512 + tid;
    s[tid] = g_raw[i] + g_raw[i + 256];
    __syncthreads();
    for (int o = 128; o > 0; o >>= 1) {
        if (tid < o) s[tid] += s[tid + o];
        __syncthreads();
    }
    if (tid == 0) g_part[blockIdx.x] = s[0];
}
__global__ void k_finish_raw() {
    __shared__ float s[256];
    int tid = threadIdx.x;
    s[tid] = g_part[tid];
    __syncthreads();
    for (int o = 128; o > 0; o >>= 1) {
        if (tid < o) s[tid] += s[tid + o];
        __syncthreads();
    }
    if (tid == 0) g_scalars[0] = s[0] * (1.f / (float)BATCH);
}
__global__ void k_reduce_lw() {
    __shared__ float s[256];
    int tid = threadIdx.x;
    float mean = g_scalars[0];
    int i = blockIdx.x * 512 + tid;
    s[tid] = expf(0.5f * tanhf(g_raw[i] - mean)) +
             expf(0.5f * tanhf(g_raw[i + 256] - mean));
    __syncthreads();
    for (int o = 128; o > 0; o >>= 1) {
        if (tid < o) s[tid] += s[tid + o];
        __syncthreads();
    }
    if (tid == 0) g_part[blockIdx.x] = s[0];
}
__global__ void k_finish_lw() {
    __shared__ float s[256];
    int tid = threadIdx.x;
    s[tid] = g_part[tid];
    __syncthreads();
    for (int o = 128; o > 0; o >>= 1) {
        if (tid < o) s[tid] += s[tid + o];
        __syncthreads();
    }
    if (tid == 0) g_scalars[1] = fmaxf(s[0] * (1.f / (float)BATCH), 1e-6f);
}
__global__ void k_write_lw(float* __restrict__ out_lw) {
    int i = blockIdx.x * 256 + threadIdx.x;
    float lw = expf(0.5f * tanhf(g_raw[i] - g_scalars[0]));
    out_lw[i] = lw / g_scalars[1];
}

// =====================================================================
extern "C" void kernel_launch(void* const* d_in, const int* in_sizes, int n_in,
                              void* d_out, int out_size) {
    const float* obs   = (const float*)d_in[0];
    const float* W1    = (const float*)d_in[1];
    const float* b1    = (const float*)d_in[2];
    const float* W2    = (const float*)d_in[3];
    const float* b2    = (const float*)d_in[4];
    const float* Wr    = (const float*)d_in[5];
    const float* br    = (const float*)d_in[6];
    const float* Win   = (const float*)d_in[7];
    const float* bin_  = (const float*)d_in[8];
    const float* Wout  = (const float*)d_in[9];
    const float* bout  = (const float*)d_in[10];
    const float* gamma = (const float*)d_in[11];
    const float* beta  = (const float*)d_in[12];
    const float* Wh1   = (const float*)d_in[13];
    const float* bh1   = (const float*)d_in[14];
    const float* Wh2   = (const float*)d_in[15];
    const float* bh2   = (const float*)d_in[16];

    float* out     = (float*)d_out;
    float* out_ctx = out;
    float* out_lw  = out + (size_t)BATCH * 64;
    float* out_ent = out_lw + BATCH;

    __nv_bfloat16* d_Cb;  cudaGetSymbolAddress((void**)&d_Cb, g_Cb);
    __nv_bfloat16* d_Hb;  cudaGetSymbolAddress((void**)&d_Hb, g_Hb);
    __nv_bfloat16* d_W1b; cudaGetSymbolAddress((void**)&d_W1b, g_W1b);
    __nv_bfloat16* d_W2b; cudaGetSymbolAddress((void**)&d_W2b, g_W2b);
    __nv_bfloat16* d_tok; cudaGetSymbolAddress((void**)&d_tok, g_tokb);

    cudaFuncSetAttribute((const void*)gemm_bf16<10, 320, true, 256>,
                         cudaFuncAttributeMaxDynamicSharedMemorySize, GEMM_SMEM_BYTES);
    cudaFuncSetAttribute((const void*)gemm_bf16<8, 256, false, 512>,
                         cudaFuncAttributeMaxDynamicSharedMemorySize, GEMM_SMEM_BYTES);
    cudaFuncSetAttribute(k3a_attn, cudaFuncAttributeMaxDynamicSharedMemorySize,
                         K3A_SMEM_BYTES);
    cudaFuncSetAttribute(k4_out_ln_head, cudaFuncAttributeMaxDynamicSharedMemorySize,
                         K4_SMEM_BYTES);

    k0_fold<<<8, 256>>>(Wr, br, Win, bin_, Wout, bout, W2, W1);
    kg_gather<<<BATCH * 160 / 256, 256>>>(obs);
    gemm_bf16<10, 320, true, 256><<<dim3(BATCH / 128, 2), 256, GEMM_SMEM_BYTES>>>(
        d_Cb, d_W1b, b1, d_Hb);
    gemm_bf16<8, 256, false, 512><<<dim3(BATCH / 128, 4), 256, GEMM_SMEM_BYTES>>>(
        d_Hb, d_W2b, b2, d_tok);
    k3a_attn<<<BATCH / 16, 256, K3A_SMEM_BYTES>>>(obs, out_ent);
    k4_out_ln_head<<<BATCH / 128, 256, K4_SMEM_BYTES>>>(
        obs, Wr, br, gamma, beta, Wh1, bh1, Wh2, bh2, out_ctx);
    k_reduce_raw<<<256, 256>>>();
    k_finish_raw<<<1, 256>>>();
    k_reduce_lw<<<256, 256>>>();
    k_finish_lw<<<1, 256>>>();
    k_write_lw<<<BATCH / 256, 256>>>(out_lw);
}

// round 17
// speedup vs baseline: 1.2057x; 1.1107x over previous
#include <cuda_runtime.h>
#include <cuda_bf16.h>
#include <math.h>

#define BATCH 131072

// tiled operands: [rowTile 128][kchunk 64] -> 16KB swizzled blocks
__device__ __nv_bfloat16 g_Cb[(size_t)BATCH * 320];
__device__ __nv_bfloat16 g_Hb[(size_t)BATCH * 256];
__device__ __nv_bfloat16 g_tokb[(size_t)BATCH * 512];
__device__ __nv_bfloat16 g_wtokb[(size_t)BATCH * 256];
__device__ float g_raw[BATCH];
__device__ float g_part[256];
__device__ float g_scalars[2];
__device__ float g_A1T[12 * 256];
__device__ float g_c1[256];
__device__ __nv_bfloat16 g_Gb[64 * 256];
__device__ float g_cb[64];
__device__ __nv_bfloat16 g_W2b[512 * 256];   // tiled
__device__ __nv_bfloat16 g_W1b[256 * 320];   // tiled

// ---------------- helpers ----------------
__device__ __forceinline__ void cp16(unsigned dst, const void* src) {
    asm volatile("cp.async.cg.shared.global [%0], [%1], 16;" ::
                 "r"(dst), "l"(src));
}
#define CP_COMMIT asm volatile("cp.async.commit_group;")
#define CP_WAIT0  asm volatile("cp.async.wait_group 0;")

__device__ __forceinline__ void mma16(float* d, const unsigned* a, const unsigned* b) {
    asm volatile(
        "mma.sync.aligned.m16n8k16.row.col.f32.bf16.bf16.f32 "
        "{%0,%1,%2,%3}, {%4,%5,%6,%7}, {%8,%9}, {%0,%1,%2,%3};"
        : "+f"(d[0]), "+f"(d[1]), "+f"(d[2]), "+f"(d[3])
        : "r"(a[0]), "r"(a[1]), "r"(a[2]), "r"(a[3]), "r"(b[0]), "r"(b[1]));
}
__device__ __forceinline__ void ldsm4(unsigned* r, unsigned addr) {
    asm volatile("ldmatrix.sync.aligned.m8n8.x4.shared.b16 {%0,%1,%2,%3}, [%4];"
                 : "=r"(r[0]), "=r"(r[1]), "=r"(r[2]), "=r"(r[3]) : "r"(addr));
}
__device__ __forceinline__ float2 bf2f(unsigned u) {
    __nv_bfloat162 b = *(__nv_bfloat162*)&u;
    return __bfloat1622float2(b);
}
// element index into tiled+swizzled layout; kch = K/64
__device__ __forceinline__ size_t tiled_idx(int row, int k, int kch) {
    size_t base = ((size_t)(row >> 7) * kch + (k >> 6)) * 8192;
    unsigned byte = (unsigned)(((row & 127) << 7) + ((k & 63) << 1));
    byte ^= (byte >> 3) & 0x70;
    return base + (byte >> 1);
}

#define MBARRIER_INIT(addr, cnt) \
    asm volatile("mbarrier.init.shared.b64 [%0], %1;" :: "r"(addr), "r"(cnt) : "memory")
#define MBARRIER_WAIT_PARITY(addr, par) do {                                   \
    unsigned _m = (addr); unsigned _p = (par); unsigned _d;                    \
    asm volatile("{\n\t.reg .pred p;\n\t"                                      \
        "mbarrier.try_wait.parity.acquire.cta.shared::cta.b64 p, [%1], %2;\n\t"\
        "selp.b32 %0, 1, 0, p;\n\t}" : "=r"(_d) : "r"(_m), "r"(_p) : "memory");\
    if (!_d) {                                                                 \
        asm volatile("{\n\t.reg .pred P1;\n\t"                                 \
            "WL_%=:\n\t"                                                       \
            "mbarrier.try_wait.parity.acquire.cta.shared::cta.b64 P1, [%0], %1, 0x989680;\n\t" \
            "@P1 bra.uni WD_%=;\n\t"                                           \
            "bra.uni WL_%=;\n\t"                                               \
            "WD_%=:\n\t}" :: "r"(_m), "r"(_p) : "memory");                     \
    }                                                                          \
} while (0)

// ============ KG: gather obs -> bf16 contact, tiled layout ============
__global__ __launch_bounds__(256) void kg_gather(const float* __restrict__ obs) {
    int idx = blockIdx.x * 256 + threadIdx.x;
    int row = idx / 160, p = idx % 160;
    int k0 = p * 2;
    float v0 = 0.f, v1 = 0.f;
    if (k0 < 308) {
        int c0 = (k0 < 224) ? 45 + k0 : 68 + k0;
        v0 = obs[(size_t)row * 376 + c0];
    }
    if (k0 + 1 < 308) {
        int c1 = (k0 + 1 < 224) ? 46 + k0 : 69 + k0;
        v1 = obs[(size_t)row * 376 + c1];
    }
    *(__nv_bfloat162*)&g_Cb[tiled_idx(row, k0, 5)] = __floats2bfloat162_rn(v0, v1);
}

// ============ K0: fold precompute + tiled bf16 weights ============
__global__ __launch_bounds__(256) void k0_fold(
    const float* __restrict__ Wr, const float* __restrict__ br,
    const float* __restrict__ Win, const float* __restrict__ bin_,
    const float* __restrict__ Wout, const float* __restrict__ bout,
    const float* __restrict__ W2, const float* __restrict__ W1) {
    __shared__ float QW[64 * 12];
    __shared__ float qsS[64];
    const int tid = threadIdx.x, bx = blockIdx.x;

    if (bx == 0) {
        for (int idx = tid; idx < 704; idx += 256) {
            int e = idx / 11, t = idx % 11;
            float acc = 0.f;
            for (int d = 0; d < 64; ++d) acc = fmaf(Win[e * 64 + d], Wr[d * 11 + t], acc);
            QW[e * 12 + t] = acc;
        }
        for (int idx = tid; idx < 64; idx += 256) {
            float acc = bin_[idx];
            for (int d = 0; d < 64; ++d) acc = fmaf(Win[idx * 64 + d], br[d], acc);
            qsS[idx] = acc;
        }
        __syncthreads();
        for (int idx = tid; idx < 2816; idx += 256) {
            int hj = idx / 11, t = idx % 11;
            int h = hj >> 6, j = hj & 63;
            float acc = 0.f;
            for (int e = 0; e < 16; ++e) {
                int x = h * 16 + e;
                acc = fmaf(Win[4096 + x * 64 + j], QW[x * 12 + t], acc);
            }
            g_A1T[t * 256 + hj] = acc;
        }
        for (int idx = tid; idx < 256; idx += 256) {
            int h = idx >> 6, j = idx & 63;
            float acc = 0.f;
            for (int e = 0; e < 16; ++e) {
                int x = h * 16 + e;
                acc = fmaf(Win[4096 + x * 64 + j], qsS[x], acc);
            }
            g_c1[idx] = acc;
        }
        for (int idx = tid; idx < 64; idx += 256) {
            float acc = bout[idx];
            for (int d = 0; d < 64; ++d) acc = fmaf(Wout[idx * 64 + d], bin_[128 + d], acc);
            g_cb[idx] = acc;
        }
    }
    for (int idx = tid; idx < 2048; idx += 256) {
        int e = bx * 8 + (idx >> 8);
        int hj = idx & 255, h = hj >> 6, j = hj & 63;
        float acc = 0.f;
        for (int d = 0; d < 16; ++d)
            acc = fmaf(Wout[e * 64 + h * 16 + d], Win[8192 + (h * 16 + d) * 64 + j], acc);
        g_Gb[e * 256 + hj] = __float2bfloat16(acc);
    }
    for (int idx = bx * 16384 + tid; idx < (bx + 1) * 16384; idx += 256) {
        int n = idx / 256, k = idx % 256;
        g_W2b[tiled_idx(n, k, 4)] = __float2bfloat16(W2[idx]);
    }
    for (int idx = bx * 10240 + tid; idx < (bx + 1) * 10240; idx += 256) {
        int n = idx / 320, k = idx % 320;
        g_W1b[tiled_idx(n, k, 5)] = __float2bfloat16((k < 308) ? W1[n * 308 + k] : 0.f);
    }
}

// ============ bf16 GEMM 128x128, BK=64, 3-stage cp.async.bulk + mbarrier ============
#define GEMM_SMEM_BYTES (3 * 32768 + 64)

template <int KCH, bool TILEC, bool RELU, int LDC>
__global__ __launch_bounds__(256) void gemm_bf16(
    const __nv_bfloat16* __restrict__ A, const __nv_bfloat16* __restrict__ W,
    const float* __restrict__ bias, __nv_bfloat16* __restrict__ C) {
    extern __shared__ __align__(16) unsigned char smraw[];
    const unsigned smem_base = (unsigned)__cvta_generic_to_shared(smraw);
    const unsigned barBase = smem_base + 3 * 32768;
    const int tid = threadIdx.x;
    const int lane = tid & 31, w = tid >> 5;
    const int wm = (w & 1) * 64, wn = (w >> 1) * 32;
    const int g = lane >> 2, tig = lane & 3;
    const int lr = lane & 7, q = lane >> 3;
    const int arow = lr + ((q & 1) << 3);
    const int akof = ((q >> 1) << 3);
    const int brow = lr + ((q >> 1) << 3);
    const int bkof = ((q & 1) << 3);

    const char* Abase = (const char*)(A + (size_t)blockIdx.x * KCH * 8192);
    const char* Bbase = (const char*)(W + (size_t)blockIdx.y * KCH * 8192);

    if (tid == 0) {
#pragma unroll
        for (int s2 = 0; s2 < 3; ++s2) MBARRIER_INIT(barBase + s2 * 8, 1);
    }
    __syncthreads();
    asm volatile("fence.proxy.async.shared::cta;" ::: "memory");

    auto issue = [&](int t) {
        const int s2 = t % 3;
        const unsigned bar = barBase + s2 * 8;
        asm volatile("mbarrier.arrive.expect_tx.shared.b64 _, [%0], %1;"
                     :: "r"(bar), "r"(32768u) : "memory");
        asm volatile(
            "cp.async.bulk.shared::cluster.global.mbarrier::complete_tx::bytes "
            "[%0], [%1], %2, [%3];"
            :: "r"(smem_base + s2 * 32768), "l"(Abase + (size_t)t * 16384),
               "r"(16384u), "r"(bar) : "memory");
        asm volatile(
            "cp.async.bulk.shared::cluster.global.mbarrier::complete_tx::bytes "
            "[%0], [%1], %2, [%3];"
            :: "r"(smem_base + s2 * 32768 + 16384), "l"(Bbase + (size_t)t * 16384),
               "r"(16384u), "r"(bar) : "memory");
    };

    if (tid == 0) { issue(0); issue(1); issue(2); }

    float acc[4][4][4] = {};

    for (int kt = 0; kt < KCH; ++kt) {
        const int s = kt % 3;
        const unsigned sA = smem_base + s * 32768;
        const unsigned sB = sA + 16384;
        MBARRIER_WAIT_PARITY(barBase + s * 8, (unsigned)((kt / 3) & 1));
#pragma unroll
        for (int km = 0; km < 4; ++km) {
            const int kf = km * 16;
            unsigned a[4][4], bb[2][4];
#pragma unroll
            for (int mt = 0; mt < 4; ++mt) {
                unsigned byte = (unsigned)(((wm + mt * 16 + arow) << 7) +
                                           ((kf + akof) << 1));
                byte ^= (byte >> 3) & 0x70;
                ldsm4(a[mt], sA + byte);
            }
#pragma unroll
            for (int p = 0; p < 2; ++p) {
                unsigned byte = (unsigned)(((wn + p * 16 + brow) << 7) +
                                           ((kf + bkof) << 1));
                byte ^= (byte >> 3) & 0x70;
                ldsm4(bb[p], sB + byte);
            }
#pragma unroll
            for (int mt = 0; mt < 4; ++mt)
#pragma unroll
                for (int nt = 0; nt < 4; ++nt)
                    mma16(acc[mt][nt], a[mt], &bb[nt >> 1][(nt & 1) * 2]);
        }
        __syncthreads();
        if (tid == 0 && kt + 3 < KCH) issue(kt + 3);
    }

    const int row0 = blockIdx.x * 128, n0 = blockIdx.y * 128;
#pragma unroll
    for (int mt = 0; mt < 4; ++mt) {
#pragma unroll
        for (int nt = 0; nt < 4; ++nt) {
            int row = row0 + wm + mt * 16 + g;
            int col = n0 + wn + nt * 8 + 2 * tig;
            float b0 = __ldg(bias + col), b1 = __ldg(bias + col + 1);
            float v0 = acc[mt][nt][0] + b0, v1 = acc[mt][nt][1] + b1;
            float v2 = acc[mt][nt][2] + b0, v3 = acc[mt][nt][3] + b1;
            if (RELU) {
                v0 = fmaxf(v0, 0.f); v1 = fmaxf(v1, 0.f);
                v2 = fmaxf(v2, 0.f); v3 = fmaxf(v3, 0.f);
            }
            if (TILEC) {
                *(__nv_bfloat162*)&C[tiled_idx(row, col, 4)] =
                    __floats2bfloat162_rn(v0, v1);
                *(__nv_bfloat162*)&C[tiled_idx(row + 8, col, 4)] =
                    __floats2bfloat162_rn(v2, v3);
            } else {
                *(__nv_bfloat162*)&C[(size_t)row * LDC + col] =
                    __floats2bfloat162_rn(v0, v1);
                *(__nv_bfloat162*)&C[(size_t)(row + 8) * LDC + col] =
                    __floats2bfloat162_rn(v2, v3);
            }
        }
    }
}

// ============ K3a: bf16 toks, block-coop s1, scores, softmax, entropy, wtok ============
#define K3A_SMEM_FLOATS 9664
#define K3A_SMEM_BYTES (K3A_SMEM_FLOATS * 4)

__global__ __launch_bounds__(256) void k3a_attn(const float* __restrict__ obs,
                                                float* __restrict__ out_ent) {
    extern __shared__ float sm[];
    __nv_bfloat16* toksb = (__nv_bfloat16*)sm;
    float* s1S   = sm + 4608;
    float* rootS = s1S + 4352;
    float* attnS = rootS + 192;

    const int tid = threadIdx.x;
    const int lane = tid & 31, w = tid >> 5;
    const int row0 = blockIdx.x * 16;

    {
        const __nv_bfloat16* src = g_tokb + (size_t)row0 * 512;
#pragma unroll
        for (int l = 0; l < 4; ++l) {
            int idx = (tid + l * 256) * 8;
            int r = idx >> 9, c = idx & 511;
            cp16((unsigned)__cvta_generic_to_shared(
                     &toksb[r * 576 + (c >> 6) * 72 + (c & 63)]),
                 src + (size_t)r * 512 + c);
        }
    }
    CP_COMMIT;
    for (int idx = tid; idx < 176; idx += 256) {
        int r = idx / 11, j = idx % 11;
        int col = (j < 5) ? j : (17 + j);
        rootS[r * 12 + j] = obs[(size_t)(row0 + r) * 376 + col];
    }
    float a1[11];
#pragma unroll
    for (int t = 0; t < 11; ++t) a1[t] = g_A1T[t * 256 + tid];
    const float c1v = g_c1[tid];
    CP_WAIT0;
    __syncthreads();

    {
        const int dst = (tid >> 6) * 68 + (tid & 63);
#pragma unroll
        for (int r = 0; r < 16; ++r) {
            float acc = c1v;
#pragma unroll
            for (int t = 0; t < 11; ++t) acc = fmaf(rootS[r * 12 + t], a1[t], acc);
            s1S[r * 272 + dst] = acc;
        }
    }
    __syncthreads();

    const int h = lane >> 3, t = lane & 7;
    const int hh = lane >> 3;
    const int jb = (lane & 7) * 8;
#pragma unroll
    for (int rr = 0; rr < 2; ++rr) {
        const int r = w * 2 + rr;
        const size_t row = (size_t)row0 + r;
        float4 sv = {0.f, 0.f, 0.f, 0.f};
        const float* s1p = &s1S[r * 272 + h * 68];
        const uint4* tpv = (const uint4*)(toksb + r * 576 + t * 72);
#pragma unroll
        for (int j8 = 0; j8 < 8; ++j8) {
            uint4 u = tpv[j8];
            float2 t0 = bf2f(u.x), t1 = bf2f(u.y), t2 = bf2f(u.z), t3 = bf2f(u.w);
            float4 a0 = *(const float4*)(s1p + 8 * j8);
            float4 a1_ = *(const float4*)(s1p + 8 * j8 + 4);
            sv.x = fmaf(a0.x, t0.x, sv.x);
            sv.y = fmaf(a0.y, t0.y, sv.y);
            sv.z = fmaf(a0.z, t1.x, sv.z);
            sv.w = fmaf(a0.w, t1.y, sv.w);
            sv.x = fmaf(a1_.x, t2.x, sv.x);
            sv.y = fmaf(a1_.y, t2.y, sv.y);
            sv.z = fmaf(a1_.z, t3.x, sv.z);
            sv.w = fmaf(a1_.w, t3.y, sv.w);
        }
        float s = (sv.x + sv.y + sv.z + sv.w) * 0.25f;
        float m = s;
        m = fmaxf(m, __shfl_xor_sync(0xffffffffu, m, 1, 8));
        m = fmaxf(m, __shfl_xor_sync(0xffffffffu, m, 2, 8));
        m = fmaxf(m, __shfl_xor_sync(0xffffffffu, m, 4, 8));
        float ex = expf(s - m);
        float den = ex;
        den += __shfl_xor_sync(0xffffffffu, den, 1, 8);
        den += __shfl_xor_sync(0xffffffffu, den, 2, 8);
        den += __shfl_xor_sync(0xffffffffu, den, 4, 8);
        float a = ex / den;
        attnS[r * 32 + lane] = a;
        float ah = a;
        ah += __shfl_xor_sync(0xffffffffu, ah, 8);
        ah += __shfl_xor_sync(0xffffffffu, ah, 16);
        float aw = fmaxf(ah * 0.25f, 1e-8f);
        float term = -aw * logf(aw);
        term += __shfl_xor_sync(0xffffffffu, term, 1, 8);
        term += __shfl_xor_sync(0xffffffffu, term, 2, 8);
        term += __shfl_xor_sync(0xffffffffu, term, 4, 8);
        if (lane == 0) out_ent[row] = term;
        __syncwarp();
        float av[8];
#pragma unroll
        for (int tt = 0; tt < 8; ++tt) av[tt] = attnS[r * 32 + hh * 8 + tt];
        float4 acc0 = {0.f, 0.f, 0.f, 0.f}, acc1 = {0.f, 0.f, 0.f, 0.f};
        const __nv_bfloat16* tb = toksb + r * 576 + jb;
#pragma unroll
        for (int tt = 0; tt < 8; ++tt) {
            uint4 u = *(const uint4*)(tb + tt * 72);
            float2 t0 = bf2f(u.x), t1 = bf2f(u.y), t2 = bf2f(u.z), t3 = bf2f(u.w);
            float av_ = av[tt];
            acc0.x = fmaf(av_, t0.x, acc0.x);
            acc0.y = fmaf(av_, t0.y, acc0.y);
            acc0.z = fmaf(av_, t1.x, acc0.z);
            acc0.w = fmaf(av_, t1.y, acc0.w);
            acc1.x = fmaf(av_, t2.x, acc1.x);
            acc1.y = fmaf(av_, t2.y, acc1.y);
            acc1.z = fmaf(av_, t3.x, acc1.z);
            acc1.w = fmaf(av_, t3.y, acc1.w);
        }
        __nv_bfloat162 pk[4];
        pk[0] = __floats2bfloat162_rn(acc0.x, acc0.y);
        pk[1] = __floats2bfloat162_rn(acc0.z, acc0.w);
        pk[2] = __floats2bfloat162_rn(acc1.x, acc1.y);
        pk[3] = __floats2bfloat162_rn(acc1.z, acc1.w);
        *(uint4*)&g_wtokb[row * 256 + lane * 8] = *(uint4*)pk;
    }
}

// ============ K4: bf16 GEMM y = wtok@G^T + cb, + remb + LN + head ============
#define K4_SMEM_FLOATS 13184
#define K4_SMEM_BYTES (K4_SMEM_FLOATS * 4)

__global__ __launch_bounds__(256) void k4_out_ln_head(
    const float* __restrict__ obs,
    const float* __restrict__ Wr, const float* __restrict__ br,
    const float* __restrict__ gamma, const float* __restrict__ beta,
    const float* __restrict__ Wh1, const float* __restrict__ bh1,
    const float* __restrict__ Wh2, const float* __restrict__ bh2,
    float* __restrict__ out_ctx) {
    extern __shared__ float sm[];
    __nv_bfloat16* Asb = (__nv_bfloat16*)sm;
    __nv_bfloat16* Bsb = Asb + 2 * 128 * 24;
    float* ys = sm;
    float* Wh1S  = sm + 8704;
    float* WrS   = sm + 10880;
    float* rootS = sm + 11648;

    const int tid = threadIdx.x;
    const int lane = tid & 31, w = tid >> 5;
    const int row0 = blockIdx.x * 128;
    const int wm = (w & 3) * 32, wn = (w >> 2) * 32;
    const int g = lane >> 2, tig = lane & 3;

    float acc[2][4][4] = {};

    auto loadTile = [&](int s, int kt) {
        const int kb = kt * 16;
        {
            int r = tid >> 1, off = (tid & 1) * 8;
            cp16((unsigned)__cvta_generic_to_shared(&Asb[(s * 128 + r) * 24 + off]),
                 g_wtokb + (size_t)(row0 + r) * 256 + kb + off);
        }
        if (tid < 128) {
            int n = tid >> 1, off = (tid & 1) * 8;
            cp16((unsigned)__cvta_generic_to_shared(&Bsb[(s * 64 + n) * 24 + off]),
                 g_Gb + (size_t)n * 256 + kb + off);
        }
    };

    loadTile(0, 0);
    CP_COMMIT;
    for (int kt = 0; kt < 16; ++kt) {
        CP_WAIT0;
        __syncthreads();
        if (kt + 1 < 16) {
            loadTile((kt + 1) & 1, kt + 1);
            CP_COMMIT;
        }
        const int s = kt & 1;
        unsigned a[2][4], b[4][2];
#pragma unroll
        for (int mt = 0; mt < 2; ++mt) {
            int r = wm + mt * 16 + g;
            a[mt][0] = *(const unsigned*)&Asb[(s * 128 + r) * 24 + tig * 2];
            a[mt][1] = *(const unsigned*)&Asb[(s * 128 + r + 8) * 24 + tig * 2];
            a[mt][2] = *(const unsigned*)&Asb[(s * 128 + r) * 24 + tig * 2 + 8];
            a[mt][3] = *(const unsigned*)&Asb[(s * 128 + r + 8) * 24 + tig * 2 + 8];
        }
#pragma unroll
        for (int nt = 0; nt < 4; ++nt) {
            int n = wn + nt * 8 + g;
            b[nt][0] = *(const unsigned*)&Bsb[(s * 64 + n) * 24 + tig * 2];
            b[nt][1] = *(const unsigned*)&Bsb[(s * 64 + n) * 24 + tig * 2 + 8];
        }
#pragma unroll
        for (int mt = 0; mt < 2; ++mt)
#pragma unroll
            for (int nt = 0; nt < 4; ++nt) mma16(acc[mt][nt], a[mt], b[nt]);
    }
    __syncthreads();

#pragma unroll
    for (int mt = 0; mt < 2; ++mt) {
#pragma unroll
        for (int nt = 0; nt < 4; ++nt) {
            int r = wm + mt * 16 + g;
            int col = wn + nt * 8 + 2 * tig;
            float c0 = g_cb[col], c1 = g_cb[col + 1];
            ys[r * 68 + col]           = acc[mt][nt][0] + c0;
            ys[r * 68 + col + 1]       = acc[mt][nt][1] + c1;
            ys[(r + 8) * 68 + col]     = acc[mt][nt][2] + c0;
            ys[(r + 8) * 68 + col + 1] = acc[mt][nt][3] + c1;
        }
    }
    for (int idx = tid; idx < 2048; idx += 256)
        Wh1S[(idx >> 6) * 68 + (idx & 63)] = Wh1[idx];
    for (int idx = tid; idx < 704; idx += 256)
        WrS[(idx / 11) * 12 + (idx % 11)] = Wr[idx];
    for (int idx = tid; idx < 1408; idx += 256) {
        int r = idx / 11, j = idx % 11;
        int col = (j < 5) ? j : (17 + j);
        rootS[r * 12 + j] = obs[(size_t)(row0 + r) * 376 + col];
    }
    __syncthreads();

    const float gm0 = gamma[lane], gm1 = gamma[lane + 32];
    const float bt0 = beta[lane],  bt1 = beta[lane + 32];
    const float br0 = br[lane],    br1 = br[lane + 32];
    const float bh1v = bh1[lane], wh2v = Wh2[lane], bh2v = bh2[0];

#pragma unroll 2
    for (int rr = 0; rr < 16; ++rr) {
        const int r = w * 16 + rr;
        const size_t row = (size_t)row0 + r;
        float e0 = br0, e1 = br1;
#pragma unroll
        for (int j = 0; j < 11; ++j) {
            float rv = rootS[r * 12 + j];
            e0 = fmaf(rv, WrS[lane * 12 + j], e0);
            e1 = fmaf(rv, WrS[(lane + 32) * 12 + j], e1);
        }
        float x0 = ys[r * 68 + lane] + e0;
        float x1 = ys[r * 68 + lane + 32] + e1;
        float ssum = x0 + x1;
#pragma unroll
        for (int o = 16; o > 0; o >>= 1) ssum += __shfl_xor_sync(0xffffffffu, ssum, o);
        float mu = ssum * (1.f / 64.f);
        float d0 = x0 - mu, d1 = x1 - mu;
        float vs = d0 * d0 + d1 * d1;
#pragma unroll
        for (int o = 16; o > 0; o >>= 1) vs += __shfl_xor_sync(0xffffffffu, vs, o);
        float inv = rsqrtf(vs * (1.f / 64.f) + 1e-5f);
        float c0 = fmaf(gm0, d0 * inv, bt0);
        float c1 = fmaf(gm1, d1 * inv, bt1);
        out_ctx[row * 64 + lane] = c0;
        out_ctx[row * 64 + lane + 32] = c1;
        ys[r * 68 + lane] = c0;
        ys[r * 68 + lane + 32] = c1;
        __syncwarp();
        float4 hv = {0.f, 0.f, 0.f, 0.f};
#pragma unroll
        for (int d4 = 0; d4 < 16; ++d4) {
            float4 yv = *(const float4*)&ys[r * 68 + 4 * d4];
            float4 wv = *(const float4*)&Wh1S[lane * 68 + 4 * d4];
            hv.x = fmaf(yv.x, wv.x, hv.x);
            hv.y = fmaf(yv.y, wv.y, hv.y);
            hv.z = fmaf(yv.z, wv.z, hv.z);
            hv.w = fmaf(yv.w, wv.w, hv.w);
        }
        float v = fmaxf(hv.x + hv.y + hv.z + hv.w + bh1v, 0.f) * wh2v;
#pragma unroll
        for (int o = 16; o > 0; o >>= 1) v += __shfl_xor_sync(0xffffffffu, v, o);
        if (lane == 0) g_raw[row] = v + bh2v;
        __syncwarp();
    }
}

// ================= batch reductions =================
__global__ void k_reduce_raw() {
    __shared__ float s[256];
    int tid = threadIdx.x;
    int i = blockIdx.x * 512 + tid;
    s[tid] = g_raw[i] + g_raw[i + 256];
    __syncthreads();
    for (int o = 128; o > 0; o >>= 1) {
        if (tid < o) s[tid] += s[tid + o];
        __syncthreads();
    }
    if (tid == 0) g_part[blockIdx.x] = s[0];
}
__global__ void k_finish_raw() {
    __shared__ float s[256];
    int tid = threadIdx.x;
    s[tid] = g_part[tid];
    __syncthreads();
    for (int o = 128; o > 0; o >>= 1) {
        if (tid < o) s[tid] += s[tid + o];
        __syncthreads();
    }
    if (tid == 0) g_scalars[0] = s[0] * (1.f / (float)BATCH);
}
__global__ void k_reduce_lw() {
    __shared__ float s[256];
    int tid = threadIdx.x;
    float mean = g_scalars[0];
    int i = blockIdx.x * 512 + tid;
    s[tid] = expf(0.5f * tanhf(g_raw[i] - mean)) +
             expf(0.5f * tanhf(g_raw[i + 256] - mean));
    __syncthreads();
    for (int o = 128; o > 0; o >>= 1) {
        if (tid < o) s[tid] += s[tid + o];
        __syncthreads();
    }
    if (tid == 0) g_part[blockIdx.x] = s[0];
}
__global__ void k_finish_lw() {
    __shared__ float s[256];
    int tid = threadIdx.x;
    s[tid] = g_part[tid];
    __syncthreads();
    for (int o = 128; o > 0; o >>= 1) {
        if (tid < o) s[tid] += s[tid + o];
        __syncthreads();
    }
    if (tid == 0) g_scalars[1] = fmaxf(s[0] * (1.f / (float)BATCH), 1e-6f);
}
__global__ void k_write_lw(float* __restrict__ out_lw) {
    int i = blockIdx.x * 256 + threadIdx.x;
    float lw = expf(0.5f * tanhf(g_raw[i] - g_scalars[0]));
    out_lw[i] = lw / g_scalars[1];
}

// =====================================================================
extern "C" void kernel_launch(void* const* d_in, const int* in_sizes, int n_in,
                              void* d_out, int out_size) {
    const float* obs   = (const float*)d_in[0];
    const float* W1    = (const float*)d_in[1];
    const float* b1    = (const float*)d_in[2];
    const float* W2    = (const float*)d_in[3];
    const float* b2    = (const float*)d_in[4];
    const float* Wr    = (const float*)d_in[5];
    const float* br    = (const float*)d_in[6];
    const float* Win   = (const float*)d_in[7];
    const float* bin_  = (const float*)d_in[8];
    const float* Wout  = (const float*)d_in[9];
    const float* bout  = (const float*)d_in[10];
    const float* gamma = (const float*)d_in[11];
    const float* beta  = (const float*)d_in[12];
    const float* Wh1   = (const float*)d_in[13];
    const float* bh1   = (const float*)d_in[14];
    const float* Wh2   = (const float*)d_in[15];
    const float* bh2   = (const float*)d_in[16];

    float* out     = (float*)d_out;
    float* out_ctx = out;
    float* out_lw  = out + (size_t)BATCH * 64;
    float* out_ent = out_lw + BATCH;

    __nv_bfloat16* d_Cb;  cudaGetSymbolAddress((void**)&d_Cb, g_Cb);
    __nv_bfloat16* d_Hb;  cudaGetSymbolAddress((void**)&d_Hb, g_Hb);
    __nv_bfloat16* d_W1b; cudaGetSymbolAddress((void**)&d_W1b, g_W1b);
    __nv_bfloat16* d_W2b; cudaGetSymbolAddress((void**)&d_W2b, g_W2b);
    __nv_bfloat16* d_tok; cudaGetSymbolAddress((void**)&d_tok, g_tokb);

    cudaFuncSetAttribute((const void*)gemm_bf16<5, true, true, 256>,
                         cudaFuncAttributeMaxDynamicSharedMemorySize, GEMM_SMEM_BYTES);
    cudaFuncSetAttribute((const void*)gemm_bf16<4, false, false, 512>,
                         cudaFuncAttributeMaxDynamicSharedMemorySize, GEMM_SMEM_BYTES);
    cudaFuncSetAttribute(k3a_attn, cudaFuncAttributeMaxDynamicSharedMemorySize,
                         K3A_SMEM_BYTES);
    cudaFuncSetAttribute(k4_out_ln_head, cudaFuncAttributeMaxDynamicSharedMemorySize,
                         K4_SMEM_BYTES);

    k0_fold<<<8, 256>>>(Wr, br, Win, bin_, Wout, bout, W2, W1);
    kg_gather<<<BATCH * 160 / 256, 256>>>(obs);
    gemm_bf16<5, true, true, 256><<<dim3(BATCH / 128, 2), 256, GEMM_SMEM_BYTES>>>(
        d_Cb, d_W1b, b1, d_Hb);
    gemm_bf16<4, false, false, 512><<<dim3(BATCH / 128, 4), 256, GEMM_SMEM_BYTES>>>(
        d_Hb, d_W2b, b2, d_tok);
    k3a_attn<<<BATCH / 16, 256, K3A_SMEM_BYTES>>>(obs, out_ent);
    k4_out_ln_head<<<BATCH / 128, 256, K4_SMEM_BYTES>>>(
        obs, Wr, br, gamma, beta, Wh1, bh1, Wh2, bh2, out_ctx);
    k_reduce_raw<<<256, 256>>>();
    k_finish_raw<<<1, 256>>>();
    k_reduce_lw<<<256, 256>>>();
    k_finish_lw<<<1, 256>>>();
    k_write_lw<<<BATCH / 256, 256>>>(out_lw);
}